// round 5
// baseline (speedup 1.0000x reference)
#include <cuda_runtime.h>
#include <cstdint>

#define BB 32
#define TT 2048
#define LL 17
#define EE 128
#define VV 100000
#define SS 128        // chunk length for backtracking
#define CC 16         // number of chunks (TT / SS)

// Scratch
__device__ float g_em[BB * TT * LL + 512];      // emissions [b][t][17] (+pad for prefetch overrun)
__device__ float g_alpha[BB * TT * LL];         // forward alphas [b][t][17]
__device__ unsigned char g_comp[BB * CC * LL];  // chunk survivor maps
__device__ unsigned char g_tag17[BB * CC * SS * LL]; // per-chunk tags for ALL 17 seeds

// a + b via FFMA imm-1.0 (exact, single rounding == FADD; rt 1 vs 2).
__device__ __forceinline__ float fadd1(float a, float b) {
    float r;
    asm("fma.rn.f32 %0, %1, 0f3F800000, %2;" : "=f"(r) : "f"(a), "f"(b));
    return r;
}

// ---------------------------------------------------------------------------
// Emissions: em[token][l] = dot(emb[text[token]], W5[:,l]) + b5[l]
// Inline int64-vs-int32 detection of `text` (deterministic).
// ---------------------------------------------------------------------------
__device__ __forceinline__ void fma4(float4& a, float xe, const float4 w) {
    a.x += xe * w.x; a.y += xe * w.y; a.z += xe * w.z; a.w += xe * w.w;
}

__global__ void __launch_bounds__(64) emis_kernel(
    const void* __restrict__ textp,
    const float* __restrict__ emb,
    const float* __restrict__ W5,
    const float* __restrict__ b5)
{
    __shared__ float sW[EE * 20];
    __shared__ float sb[20];
    int tid = threadIdx.x;

    // dtype detection: all of the first 512 u64 words < V  <=>  int64 storage
    const unsigned long long* t64 = (const unsigned long long*)textp;
    int ok = 1;
    for (int i = tid; i < 512; i += 64)
        if (t64[i] >= (unsigned long long)VV) ok = 0;

    for (int i = tid; i < EE * 20; i += 64) sW[i] = 0.0f;
    if (tid < 20) sb[tid] = 0.0f;
    int is64 = __syncthreads_and(ok);
    for (int i = tid; i < EE * LL; i += 64) {
        int e = i / LL, l = i % LL;
        sW[e * 20 + l] = W5[i];
    }
    if (tid < LL) sb[tid] = b5[tid];
    __syncthreads();

    int token = blockIdx.x * 64 + tid;
    int idx;
    if (is64) idx = (int)((const unsigned long long*)textp)[token];
    else      idx = ((const int*)textp)[token];
    idx = max(0, min(VV - 1, idx));

    const float4* row = (const float4*)(emb + (size_t)idx * EE);
    float4 a0 = *(const float4*)&sb[0];
    float4 a1 = *(const float4*)&sb[4];
    float4 a2 = *(const float4*)&sb[8];
    float4 a3 = *(const float4*)&sb[12];
    float4 a4 = *(const float4*)&sb[16];

#pragma unroll 4
    for (int e4 = 0; e4 < EE / 4; e4++) {
        float4 x = __ldg(&row[e4]);
        const float* wb = &sW[e4 * 4 * 20];
#pragma unroll
        for (int c = 0; c < 4; c++) {
            float xe = (c == 0) ? x.x : (c == 1) ? x.y : (c == 2) ? x.z : x.w;
            const float4* w4 = (const float4*)(wb + c * 20);
            fma4(a0, xe, w4[0]);
            fma4(a1, xe, w4[1]);
            fma4(a2, xe, w4[2]);
            fma4(a3, xe, w4[3]);
            fma4(a4, xe, w4[4]);
        }
    }

    float* o = g_em + (size_t)token * LL;
    o[0] = a0.x; o[1] = a0.y; o[2] = a0.z; o[3] = a0.w;
    o[4] = a1.x; o[5] = a1.y; o[6] = a1.z; o[7] = a1.w;
    o[8] = a2.x; o[9] = a2.y; o[10] = a2.z; o[11] = a2.w;
    o[12] = a3.x; o[13] = a3.y; o[14] = a3.z; o[15] = a3.w;
    o[16] = a4.x;
}

// ---------------------------------------------------------------------------
// argmax over 17 values, FIRST-index tie-break (matches jnp.argmax).
// ---------------------------------------------------------------------------
__device__ __forceinline__ void argmax17(const float* s, float& bv, int& bi) {
    float v[9]; int ix[9];
#pragma unroll
    for (int k = 0; k < 8; k++) {
        bool g = s[2 * k + 1] > s[2 * k];
        v[k]  = g ? s[2 * k + 1] : s[2 * k];
        ix[k] = g ? 2 * k + 1 : 2 * k;
    }
    v[8] = s[16]; ix[8] = 16;
#pragma unroll
    for (int k = 0; k < 4; k++) {
        bool g = v[2 * k + 1] > v[2 * k];
        v[k]  = g ? v[2 * k + 1] : v[2 * k];
        ix[k] = g ? ix[2 * k + 1] : ix[2 * k];
    }
    { bool g = v[1] > v[0]; v[0] = g ? v[1] : v[0]; ix[0] = g ? ix[1] : ix[0]; }
    { bool g = v[3] > v[2]; v[2] = g ? v[3] : v[2]; ix[2] = g ? ix[3] : ix[2]; }
    { bool g = v[2] > v[0]; v[0] = g ? v[2] : v[0]; ix[0] = g ? ix[2] : ix[0]; }
    { bool g = v[8] > v[0]; v[0] = g ? v[8] : v[0]; ix[0] = g ? ix[8] : ix[0]; }
    bv = v[0]; bi = ix[0];
}

// Max-only step (max exactly associative -> bitwise reference value).
// Ternary fmax nesting invites FMNMX3 fusion.
__device__ __forceinline__ float step_max(float alpha, const float* trc) {
    float s[LL];
#pragma unroll
    for (int j = 0; j < LL; j++)
        s[j] = fadd1(__shfl_sync(0xFFFFFFFFu, alpha, j), trc[j]);
    float m0 = fmaxf(fmaxf(s[0],  s[1]),  s[2]);
    float m1 = fmaxf(fmaxf(s[3],  s[4]),  s[5]);
    float m2 = fmaxf(fmaxf(s[6],  s[7]),  s[8]);
    float m3 = fmaxf(fmaxf(s[9],  s[10]), s[11]);
    float m4 = fmaxf(fmaxf(s[12], s[13]), s[14]);
    float m5 = fmaxf(s[15], s[16]);
    float a0 = fmaxf(fmaxf(m0, m1), m2);
    float a1 = fmaxf(fmaxf(m3, m4), m5);
    return fmaxf(a0, a1);
}

// ---------------------------------------------------------------------------
// Forward: one warp handles TWO interleaved batch chains (lane = label for
// both). Independent chains fill each other's latency bubbles.
// Depth-8 em prefetch ring per chain. Stores alpha vector per step.
// ---------------------------------------------------------------------------
__global__ void __launch_bounds__(32, 1) forward_kernel(
    const float* __restrict__ trans)
{
    const int b0 = blockIdx.x * 2;       // 16 blocks -> batches {b0, b0+1}
    const int l = threadIdx.x;
    const int le = (l < LL) ? l : 0;
    const bool act = (l < LL);

    float trc[LL];
#pragma unroll
    for (int j = 0; j < LL; j++) trc[j] = act ? trans[j * LL + le] : 0.0f;

    const float* emA = g_em + (size_t)b0 * TT * LL;
    const float* emB = g_em + (size_t)(b0 + 1) * TT * LL;
    float* paA = g_alpha + (size_t)b0 * TT * LL + l;
    float* paB = g_alpha + (size_t)(b0 + 1) * TT * LL + l;

    float alphaA = act ? emA[le] : -3.0e38f;
    float alphaB = act ? emB[le] : -3.0e38f;
    if (act) { paA[0] = alphaA; paB[0] = alphaB; }

    float ringA[8], ringB[8];
#pragma unroll
    for (int i = 0; i < 8; i++) {
        ringA[i] = __ldg(emA + (1 + i) * LL + le);
        ringB[i] = __ldg(emB + (1 + i) * LL + le);
    }
    const float* pfA = emA + 9 * LL + le;
    const float* pfB = emB + 9 * LL + le;
    float* psA = paA + LL;
    float* psB = paB + LL;

    // t = 1 .. 2040 in 255 blocks of 8
    for (int blk = 0; blk < 255; blk++) {
#pragma unroll
        for (int u = 0; u < 8; u++) {
            float ecA = ringA[u];
            float ecB = ringB[u];
            ringA[u] = __ldg(pfA + u * LL);          // t+8 (pad covers overrun)
            ringB[u] = __ldg(pfB + u * LL);
            alphaA = fadd1(step_max(alphaA, trc), ecA);
            alphaB = fadd1(step_max(alphaB, trc), ecB);
            if (act) { psA[u * LL] = alphaA; psB[u * LL] = alphaB; }
        }
        pfA += 8 * LL; pfB += 8 * LL;
        psA += 8 * LL; psB += 8 * LL;
    }
    // tail t = 2041..2047
#pragma unroll
    for (int u = 0; u < 7; u++) {
        alphaA = fadd1(step_max(alphaA, trc), ringA[u]);
        alphaB = fadd1(step_max(alphaB, trc), ringB[u]);
        if (act) { psA[u * LL] = alphaA; psB[u * LL] = alphaB; }
    }
}

// ---------------------------------------------------------------------------
// bp_kernel: per (b, chunk). Recompute backpointers from stored alphas
// (bitwise identical scores), walk ALL 17 possible seeds recording the tag
// sequence -> g_tag17, plus the chunk composition map -> g_comp.
// ---------------------------------------------------------------------------
__global__ void __launch_bounds__(256) bp_kernel(const float* __restrict__ trans)
{
    __shared__ float aS[(SS + 1) * LL];
    __shared__ float tS[LL * LL];
    __shared__ unsigned char bpS[SS * LL];
    __shared__ unsigned char tag17S[SS * LL];

    const int tid = threadIdx.x;
    const int b = blockIdx.x / CC, c = blockIdx.x % CC;
    const int t0 = c * SS;
    const int nrows = (c == CC - 1) ? SS : (SS + 1);
    const int nbp   = (c == CC - 1) ? (SS - 1) : SS;

    const float* src = g_alpha + ((size_t)b * TT + t0) * LL;
    for (int i = tid; i < nrows * LL; i += 256) aS[i] = src[i];
    for (int i = tid; i < LL * LL; i += 256) tS[i] = trans[i];
    __syncthreads();

    if (tid < 2 * nbp) {
        const int t = tid >> 1;
        const int h = tid & 1;
        float a[LL];
#pragma unroll
        for (int k = 0; k < LL; k++) a[k] = aS[t * LL + k];
        const int l0 = h ? 9 : 0;
        const int l1 = h ? LL : 9;
#pragma unroll 1
        for (int lcur = l0; lcur < l1; lcur++) {
            float s[LL];
#pragma unroll
            for (int k = 0; k < LL; k++) s[k] = a[k] + tS[k * LL + lcur];
            float bv; int bi;
            argmax17(s, bv, bi);
            bpS[t * LL + lcur] = (unsigned char)bi;
        }
    }
    __syncthreads();

    if (tid < LL) {   // walk all 17 seeds, record every intermediate tag
        int cur = tid;
        for (int i = nbp - 1; i >= 0; i--) {
            cur = bpS[i * LL + cur];
            tag17S[i * LL + tid] = (unsigned char)cur;
        }
        g_comp[(b * CC + c) * LL + tid] = (unsigned char)cur;
    }
    __syncthreads();

    unsigned char* tdst = g_tag17 + ((size_t)(b * CC + c) * SS) * LL;
    for (int i = tid; i < nbp * LL; i += 256) tdst[i] = tag17S[i];
}

// ---------------------------------------------------------------------------
// tags_kernel: per (b, chunk). Derive the chunk seed via the comp-map chain,
// then pure table lookup into g_tag17. Block c==0 writes score/text_lens.
// ---------------------------------------------------------------------------
__global__ void __launch_bounds__(128) tags_kernel(float* __restrict__ out)
{
    __shared__ unsigned char compS[CC * LL];
    __shared__ float afin[LL];
    __shared__ int seedS;

    const int tid = threadIdx.x;
    const int b = blockIdx.x / CC, c = blockIdx.x % CC;
    const int t0 = c * SS;
    const int nbp = (c == CC - 1) ? (SS - 1) : SS;

    for (int i = tid; i < CC * LL; i += 128) compS[i] = g_comp[b * CC * LL + i];
    if (tid < LL) afin[tid] = g_alpha[((size_t)b * TT + TT - 1) * LL + tid];
    __syncthreads();

    if (tid == 0) {
        float bv = afin[0]; int bi = 0;
        for (int j = 1; j < LL; j++) if (afin[j] > bv) { bv = afin[j]; bi = j; }
        if (c == 0) {
            out[BB * TT + b] = bv;
            out[BB * TT + BB + b] = (float)TT;
        }
        int cur = bi;                       // tag at t = 2047
        for (int cc = CC - 1; cc >= c + 1; cc--) cur = compS[cc * LL + cur];
        seedS = cur;                        // tag at t = 128*(c+1) (or 2047 if c==15)
    }
    __syncthreads();

    const int seed = seedS;
    const unsigned char* tsrc = g_tag17 + ((size_t)(b * CC + c) * SS) * LL;
    float val = (tid < nbp) ? (float)tsrc[tid * LL + seed] : (float)seed;
    out[(size_t)b * TT + t0 + tid] = val;
}

// ---------------------------------------------------------------------------
extern "C" void kernel_launch(void* const* d_in, const int* in_sizes, int n_in,
                              void* d_out, int out_size)
{
    (void)in_sizes; (void)n_in; (void)out_size;
    const void*  text  = d_in[0];
    const float* emb   = (const float*)d_in[1];
    const float* W5    = (const float*)d_in[2];
    const float* b5    = (const float*)d_in[3];
    const float* trans = (const float*)d_in[4];
    float* out = (float*)d_out;

    emis_kernel<<<(BB * TT) / 64, 64>>>(text, emb, W5, b5);
    forward_kernel<<<BB / 2, 32>>>(trans);
    bp_kernel<<<BB * CC, 256>>>(trans);
    tags_kernel<<<BB * CC, 128>>>(out);
}

// round 6
// speedup vs baseline: 1.4290x; 1.4290x over previous
#include <cuda_runtime.h>
#include <cstdint>

#define BB 32
#define TT 2048
#define LL 17
#define EE 128
#define VV 100000
#define SS 128        // chunk length for backtracking
#define CC 16         // number of chunks (TT / SS)

// Scratch
__device__ float g_em[BB * TT * LL + 512];      // emissions [b][t][17] (+pad for prefetch overrun)
__device__ float g_alpha[BB * TT * LL];         // forward alphas [b][t][17]
__device__ unsigned char g_comp[BB * CC * LL];  // chunk survivor maps
__device__ unsigned char g_tag17[BB * CC * SS * LL]; // per-chunk tags for ALL 17 seeds

// a + b via FFMA imm-1.0 (exact, single rounding == FADD; imm-form rt 1).
__device__ __forceinline__ float fadd1(float a, float b) {
    float r;
    asm("fma.rn.f32 %0, %1, 0f3F800000, %2;" : "=f"(r) : "f"(a), "f"(b));
    return r;
}

// ---------------------------------------------------------------------------
// Emissions: em[token][l] = dot(emb[text[token]], W5[:,l]) + b5[l]
// Inline int64-vs-int32 detection of `text` (deterministic).
// ---------------------------------------------------------------------------
__device__ __forceinline__ void fma4(float4& a, float xe, const float4 w) {
    a.x += xe * w.x; a.y += xe * w.y; a.z += xe * w.z; a.w += xe * w.w;
}

__global__ void __launch_bounds__(64) emis_kernel(
    const void* __restrict__ textp,
    const float* __restrict__ emb,
    const float* __restrict__ W5,
    const float* __restrict__ b5)
{
    __shared__ float sW[EE * 20];
    __shared__ float sb[20];
    int tid = threadIdx.x;

    // dtype detection: all of the first 512 u64 words < V  <=>  int64 storage
    const unsigned long long* t64 = (const unsigned long long*)textp;
    int ok = 1;
    for (int i = tid; i < 512; i += 64)
        if (t64[i] >= (unsigned long long)VV) ok = 0;

    for (int i = tid; i < EE * 20; i += 64) sW[i] = 0.0f;
    if (tid < 20) sb[tid] = 0.0f;
    int is64 = __syncthreads_and(ok);
    for (int i = tid; i < EE * LL; i += 64) {
        int e = i / LL, l = i % LL;
        sW[e * 20 + l] = W5[i];
    }
    if (tid < LL) sb[tid] = b5[tid];
    __syncthreads();

    int token = blockIdx.x * 64 + tid;
    int idx;
    if (is64) idx = (int)((const unsigned long long*)textp)[token];
    else      idx = ((const int*)textp)[token];
    idx = max(0, min(VV - 1, idx));

    const float4* row = (const float4*)(emb + (size_t)idx * EE);
    float4 a0 = *(const float4*)&sb[0];
    float4 a1 = *(const float4*)&sb[4];
    float4 a2 = *(const float4*)&sb[8];
    float4 a3 = *(const float4*)&sb[12];
    float4 a4 = *(const float4*)&sb[16];

#pragma unroll 4
    for (int e4 = 0; e4 < EE / 4; e4++) {
        float4 x = __ldg(&row[e4]);
        const float* wb = &sW[e4 * 4 * 20];
#pragma unroll
        for (int c = 0; c < 4; c++) {
            float xe = (c == 0) ? x.x : (c == 1) ? x.y : (c == 2) ? x.z : x.w;
            const float4* w4 = (const float4*)(wb + c * 20);
            fma4(a0, xe, w4[0]);
            fma4(a1, xe, w4[1]);
            fma4(a2, xe, w4[2]);
            fma4(a3, xe, w4[3]);
            fma4(a4, xe, w4[4]);
        }
    }

    float* o = g_em + (size_t)token * LL;
    o[0] = a0.x; o[1] = a0.y; o[2] = a0.z; o[3] = a0.w;
    o[4] = a1.x; o[5] = a1.y; o[6] = a1.z; o[7] = a1.w;
    o[8] = a2.x; o[9] = a2.y; o[10] = a2.z; o[11] = a2.w;
    o[12] = a3.x; o[13] = a3.y; o[14] = a3.z; o[15] = a3.w;
    o[16] = a4.x;
}

// ---------------------------------------------------------------------------
// argmax over 17 values, FIRST-index tie-break (matches jnp.argmax).
// ---------------------------------------------------------------------------
__device__ __forceinline__ void argmax17(const float* s, float& bv, int& bi) {
    float v[9]; int ix[9];
#pragma unroll
    for (int k = 0; k < 8; k++) {
        bool g = s[2 * k + 1] > s[2 * k];
        v[k]  = g ? s[2 * k + 1] : s[2 * k];
        ix[k] = g ? 2 * k + 1 : 2 * k;
    }
    v[8] = s[16]; ix[8] = 16;
#pragma unroll
    for (int k = 0; k < 4; k++) {
        bool g = v[2 * k + 1] > v[2 * k];
        v[k]  = g ? v[2 * k + 1] : v[2 * k];
        ix[k] = g ? ix[2 * k + 1] : ix[2 * k];
    }
    { bool g = v[1] > v[0]; v[0] = g ? v[1] : v[0]; ix[0] = g ? ix[1] : ix[0]; }
    { bool g = v[3] > v[2]; v[2] = g ? v[3] : v[2]; ix[2] = g ? ix[3] : ix[2]; }
    { bool g = v[2] > v[0]; v[0] = g ? v[2] : v[0]; ix[0] = g ? ix[2] : ix[0]; }
    { bool g = v[8] > v[0]; v[0] = g ? v[8] : v[0]; ix[0] = g ? ix[8] : ix[0]; }
    bv = v[0]; bi = ix[0];
}

// ---------------------------------------------------------------------------
// Forward: one warp per batch, lane = label. Alpha broadcast through SMEM
// (1 STS + BAR + 5x LDS.128) instead of 17 SHFLs. Max-only (exact: same
// candidate adds as reference; max is associative). Depth-8 em prefetch.
// ---------------------------------------------------------------------------
__global__ void __launch_bounds__(32, 1) forward_kernel(
    const float* __restrict__ trans)
{
    __shared__ float sA[20];              // alpha vector, padded to 5 float4

    const int b = blockIdx.x;
    const int l = threadIdx.x;
    const int le = (l < LL) ? l : 0;
    const bool act = (l < LL);

    float trc[LL];
#pragma unroll
    for (int j = 0; j < LL; j++) trc[j] = act ? trans[j * LL + le] : 0.0f;

    const float* em = g_em + (size_t)b * TT * LL;
    float alpha = act ? em[le] : 0.0f;
    if (l >= LL && l < 20) sA[l] = -3.0e38f;   // pad (never used in max)
    if (act) sA[l] = alpha;
    float* pa = g_alpha + (size_t)b * TT * LL + l;
    if (act) pa[0] = alpha;
    __syncthreads();

    float ring[8];
#pragma unroll
    for (int i = 0; i < 8; i++) ring[i] = __ldg(em + (1 + i) * LL + le);
    const float* pf = em + 9 * LL + le;
    float* ps = pa + LL;

    const float4* sA4 = (const float4*)sA;

    // t = 1 .. 2040 in 255 blocks of 8, then 7-step tail
    for (int blk = 0; blk < 256; blk++) {
        const int nstep = (blk < 255) ? 8 : 7;
#pragma unroll 8
        for (int u = 0; u < nstep; u++) {
            // broadcast-read previous alpha vector (all lanes same addresses)
            float4 v0 = sA4[0];
            float4 v1 = sA4[1];
            float4 v2 = sA4[2];
            float4 v3 = sA4[3];
            float  vg = sA[16];

            float emc = ring[u];
            if (blk < 255) ring[u] = __ldg(pf + u * LL);   // t+8 prefetch

            float s0  = fadd1(v0.x, trc[0]);
            float s1  = fadd1(v0.y, trc[1]);
            float s2  = fadd1(v0.z, trc[2]);
            float s3  = fadd1(v0.w, trc[3]);
            float s4  = fadd1(v1.x, trc[4]);
            float s5  = fadd1(v1.y, trc[5]);
            float s6  = fadd1(v1.z, trc[6]);
            float s7  = fadd1(v1.w, trc[7]);
            float s8  = fadd1(v2.x, trc[8]);
            float s9  = fadd1(v2.y, trc[9]);
            float s10 = fadd1(v2.z, trc[10]);
            float s11 = fadd1(v2.w, trc[11]);
            float s12 = fadd1(v3.x, trc[12]);
            float s13 = fadd1(v3.y, trc[13]);
            float s14 = fadd1(v3.w, trc[15]);  // note: s14 slot = label 15
            float s15 = fadd1(v3.z, trc[14]);  // s15 slot = label 14 (order-free: max assoc/comm)
            float s16 = fadd1(vg,   trc[16]);

            // balanced 5-level pairwise max (exact)
            float t0 = fmaxf(s0, s1),  t1 = fmaxf(s2, s3);
            float t2 = fmaxf(s4, s5),  t3 = fmaxf(s6, s7);
            float t4 = fmaxf(s8, s9),  t5 = fmaxf(s10, s11);
            float t6 = fmaxf(s12, s13), t7 = fmaxf(s14, s15);
            float u0 = fmaxf(t0, t1), u1 = fmaxf(t2, t3);
            float u2 = fmaxf(t4, t5), u3 = fmaxf(t6, t7);
            float w0 = fmaxf(u0, u1), w1 = fmaxf(u2, u3);
            float m  = fmaxf(fmaxf(w0, w1), s16);

            alpha = fadd1(m, emc);
            __syncthreads();                 // everyone done reading old sA
            if (act) sA[l] = alpha;
            __syncthreads();                 // STS drained; new sA visible
            if (act) ps[u * LL] = alpha;
        }
        pf += 8 * LL;
        ps += 8 * LL;
    }
}

// ---------------------------------------------------------------------------
// bp_kernel: per (b, chunk). Recompute backpointers from stored alphas
// (bitwise identical scores), walk ALL 17 possible seeds recording the tag
// sequence -> g_tag17, plus the chunk composition map -> g_comp.
// ---------------------------------------------------------------------------
__global__ void __launch_bounds__(256) bp_kernel(const float* __restrict__ trans)
{
    __shared__ float aS[(SS + 1) * LL];
    __shared__ float tS[LL * LL];
    __shared__ unsigned char bpS[SS * LL];
    __shared__ unsigned char tag17S[SS * LL];

    const int tid = threadIdx.x;
    const int b = blockIdx.x / CC, c = blockIdx.x % CC;
    const int t0 = c * SS;
    const int nrows = (c == CC - 1) ? SS : (SS + 1);
    const int nbp   = (c == CC - 1) ? (SS - 1) : SS;

    const float* src = g_alpha + ((size_t)b * TT + t0) * LL;
    for (int i = tid; i < nrows * LL; i += 256) aS[i] = src[i];
    for (int i = tid; i < LL * LL; i += 256) tS[i] = trans[i];
    __syncthreads();

    if (tid < 2 * nbp) {
        const int t = tid >> 1;
        const int h = tid & 1;
        float a[LL];
#pragma unroll
        for (int k = 0; k < LL; k++) a[k] = aS[t * LL + k];
        const int l0 = h ? 9 : 0;
        const int l1 = h ? LL : 9;
#pragma unroll 1
        for (int lcur = l0; lcur < l1; lcur++) {
            float s[LL];
#pragma unroll
            for (int k = 0; k < LL; k++) s[k] = a[k] + tS[k * LL + lcur];
            float bv; int bi;
            argmax17(s, bv, bi);
            bpS[t * LL + lcur] = (unsigned char)bi;
        }
    }
    __syncthreads();

    if (tid < LL) {   // walk all 17 seeds, record every intermediate tag
        int cur = tid;
        for (int i = nbp - 1; i >= 0; i--) {
            cur = bpS[i * LL + cur];
            tag17S[i * LL + tid] = (unsigned char)cur;
        }
        g_comp[(b * CC + c) * LL + tid] = (unsigned char)cur;
    }
    __syncthreads();

    unsigned char* tdst = g_tag17 + ((size_t)(b * CC + c) * SS) * LL;
    for (int i = tid; i < nbp * LL; i += 256) tdst[i] = tag17S[i];
}

// ---------------------------------------------------------------------------
// tags_kernel: per (b, chunk). Derive the chunk seed via the comp-map chain,
// then pure table lookup into g_tag17. Block c==0 writes score/text_lens.
// ---------------------------------------------------------------------------
__global__ void __launch_bounds__(128) tags_kernel(float* __restrict__ out)
{
    __shared__ unsigned char compS[CC * LL];
    __shared__ float afin[LL];
    __shared__ int seedS;

    const int tid = threadIdx.x;
    const int b = blockIdx.x / CC, c = blockIdx.x % CC;
    const int t0 = c * SS;
    const int nbp = (c == CC - 1) ? (SS - 1) : SS;

    for (int i = tid; i < CC * LL; i += 128) compS[i] = g_comp[b * CC * LL + i];
    if (tid < LL) afin[tid] = g_alpha[((size_t)b * TT + TT - 1) * LL + tid];
    __syncthreads();

    if (tid == 0) {
        float bv = afin[0]; int bi = 0;
        for (int j = 1; j < LL; j++) if (afin[j] > bv) { bv = afin[j]; bi = j; }
        if (c == 0) {
            out[BB * TT + b] = bv;
            out[BB * TT + BB + b] = (float)TT;
        }
        int cur = bi;                       // tag at t = 2047
        for (int cc = CC - 1; cc >= c + 1; cc--) cur = compS[cc * LL + cur];
        seedS = cur;                        // tag at t = 128*(c+1) (or 2047 if c==15)
    }
    __syncthreads();

    const int seed = seedS;
    const unsigned char* tsrc = g_tag17 + ((size_t)(b * CC + c) * SS) * LL;
    float val = (tid < nbp) ? (float)tsrc[tid * LL + seed] : (float)seed;
    out[(size_t)b * TT + t0 + tid] = val;
}

// ---------------------------------------------------------------------------
extern "C" void kernel_launch(void* const* d_in, const int* in_sizes, int n_in,
                              void* d_out, int out_size)
{
    (void)in_sizes; (void)n_in; (void)out_size;
    const void*  text  = d_in[0];
    const float* emb   = (const float*)d_in[1];
    const float* W5    = (const float*)d_in[2];
    const float* b5    = (const float*)d_in[3];
    const float* trans = (const float*)d_in[4];
    float* out = (float*)d_out;

    emis_kernel<<<(BB * TT) / 64, 64>>>(text, emb, W5, b5);
    forward_kernel<<<BB, 32>>>(trans);
    bp_kernel<<<BB * CC, 256>>>(trans);
    tags_kernel<<<BB * CC, 128>>>(out);
}